// round 2
// baseline (speedup 1.0000x reference)
#include <cuda_runtime.h>
#include <math.h>

// Problem constants: B=1024, H=32, N=25, F=D=128
#define BH      32768          // B*H rows
#define NNEIGH  25
#define NK      26             // self + neighbours
#define FDIM    128
#define DDIM    128
#define XN_ROW  (NNEIGH * FDIM)   // 3200 floats per (b,h) in x_neigh
#define XS_STRIDE 132             // padded row stride in floats (33 float4)

// Scratch (device globals: allocation-free per harness rules)
__device__ float g_wa[2 * FDIM];             // [0:128) = W@a_self, [128:256) = W@a_neigh
__device__ float g_xagg[(size_t)BH * FDIM];  // aggregated input rows, 16 MB

// ---------------------------------------------------------------------------
// Kernel 0: wa = W @ a  (two 128-length GEMVs). 16 blocks x 256 thr,
// one warp per output element f.
// ---------------------------------------------------------------------------
__global__ void __launch_bounds__(256)
wa_kernel(const float* __restrict__ W,
          const float* __restrict__ a_s,
          const float* __restrict__ a_n) {
    const int warp = threadIdx.x >> 5, lane = threadIdx.x & 31;
    const int f = blockIdx.x * 8 + warp;   // 0..127
    const float* wr = W + (size_t)f * DDIM;
    float s = 0.f, n = 0.f;
#pragma unroll
    for (int j = 0; j < 4; j++) {
        int d = lane + 32 * j;
        float w = wr[d];
        s = fmaf(w, a_s[d], s);
        n = fmaf(w, a_n[d], n);
    }
#pragma unroll
    for (int o = 16; o; o >>= 1) {
        s += __shfl_xor_sync(0xffffffffu, s, o);
        n += __shfl_xor_sync(0xffffffffu, n, o);
    }
    if (lane == 0) {
        g_wa[f]        = s;
        g_wa[FDIM + f] = n;
    }
}

// ---------------------------------------------------------------------------
// Kernel 1: per (b,h) attention aggregation in input space.
// One block per row (32768 blocks), 128 threads (4 warps).
// Scores: 4 lanes per dot (quad), only 2 shuffles per reduction.
// ---------------------------------------------------------------------------
__global__ void __launch_bounds__(128)
agg_kernel(const float* __restrict__ x_self,
           const float* __restrict__ x_neigh) {
    __shared__ float xs[NK * XS_STRIDE];   // 26 padded rows, row0 = self (~13.4 KB)
    __shared__ float wa_s[FDIM];
    __shared__ float wa_n[FDIM];
    __shared__ float sc[32];               // [0..25] scores->probs, [26] = self score

    const int t   = threadIdx.x;
    const int row = blockIdx.x;

    wa_s[t] = g_wa[t];
    wa_n[t] = g_wa[FDIM + t];

    // stage self row (row 0)
    xs[t] = x_self[(size_t)row * FDIM + t];

    // stage neighbour rows via float4 (800 vec4), padded row stride of 33 vec4
    const float4* xn  = reinterpret_cast<const float4*>(x_neigh + (size_t)row * XN_ROW);
    float4*       xs4 = reinterpret_cast<float4*>(xs);
    for (int i = t; i < XN_ROW / 4; i += 128) {
        int n = i >> 5, j = i & 31;
        xs4[(n + 1) * (XS_STRIDE / 4) + j] = xn[i];
    }
    __syncthreads();

    // 27 dots of length 128: quad (k4 = t>>2) owns dot k4; lane g = t&3
    // k4 in [0,26): xs row k4 . wa_n ; k4 == 26: xs row 0 . wa_s
    const int k4 = t >> 2, g = t & 3;
    float v = 0.f;
    if (k4 < 27) {
        const int   r  = (k4 == 26) ? 0 : k4;
        const float4* xr = reinterpret_cast<const float4*>(xs + r * XS_STRIDE);
        const float4* wv = reinterpret_cast<const float4*>((k4 == 26) ? wa_s : wa_n);
#pragma unroll
        for (int j = 0; j < 8; j++) {
            float4 x4 = xr[g + 4 * j];
            float4 w4 = wv[g + 4 * j];
            v = fmaf(x4.x, w4.x, v);
            v = fmaf(x4.y, w4.y, v);
            v = fmaf(x4.z, w4.z, v);
            v = fmaf(x4.w, w4.w, v);
        }
    }
    v += __shfl_xor_sync(0xffffffffu, v, 1);
    v += __shfl_xor_sync(0xffffffffu, v, 2);
    if (g == 0 && k4 < 27) sc[k4] = v;
    __syncthreads();

    // softmax over the 26 entries (warp 0)
    if (t < 32) {
        const int lane = t;
        float ss = sc[26];
        float u  = -INFINITY;
        if (lane < NK) {
            u = ss + sc[lane];
            u = (u > 0.f) ? u : 0.2f * u;   // LeakyReLU(0.2)
        }
        float m = u;
#pragma unroll
        for (int o = 16; o; o >>= 1) m = fmaxf(m, __shfl_xor_sync(0xffffffffu, m, o));
        float e = (lane < NK) ? expf(u - m) : 0.f;
        float s = e;
#pragma unroll
        for (int o = 16; o; o >>= 1) s += __shfl_xor_sync(0xffffffffu, s, o);
        if (lane < NK) sc[lane] = e / s;
    }
    __syncthreads();

    // x_agg[f] = sum_k p_k * x_all[k][f]   (conflict-free: t consecutive)
    float acc = 0.f;
#pragma unroll
    for (int k = 0; k < NK; k++) acc = fmaf(sc[k], xs[k * XS_STRIDE + t], acc);
    g_xagg[(size_t)row * FDIM + t] = acc;
}

// ---------------------------------------------------------------------------
// Kernel 2: out = relu(g_xagg[32768,128] @ W[128,128])
// Classic smem-tiled SGEMM: BM=BN=128, BK=16, 256 threads, 8x8 micro-tile.
// ---------------------------------------------------------------------------
#define K2_BM 128
#define K2_BN 128
#define K2_BK 16

__global__ void __launch_bounds__(256)
gemm_relu_kernel(const float* __restrict__ W, float* __restrict__ out) {
    __shared__ float As[K2_BK][K2_BM];
    __shared__ float Bs[K2_BK][K2_BN];

    const int tid = threadIdx.x;
    const int ty  = tid >> 4;       // 0..15 -> row group
    const int tx  = tid & 15;       // 0..15 -> col group
    const size_t rowbase = (size_t)blockIdx.x * K2_BM;

    float acc[8][8];
#pragma unroll
    for (int i = 0; i < 8; i++)
#pragma unroll
        for (int j = 0; j < 8; j++) acc[i][j] = 0.f;

    for (int k0 = 0; k0 < FDIM; k0 += K2_BK) {
        // load A tile 128x16 (transposed into As[k][r])
#pragma unroll
        for (int i = tid; i < K2_BM * K2_BK; i += 256) {
            int r = i >> 4, k = i & 15;
            As[k][r] = g_xagg[(rowbase + r) * FDIM + k0 + k];
        }
        // load B tile 16x128
#pragma unroll
        for (int i = tid; i < K2_BK * K2_BN; i += 256) {
            int k = i >> 7, d = i & 127;
            Bs[k][d] = W[(size_t)(k0 + k) * DDIM + d];
        }
        __syncthreads();

#pragma unroll
        for (int kk = 0; kk < K2_BK; kk++) {
            float a[8], b[8];
            *reinterpret_cast<float4*>(&a[0]) = *reinterpret_cast<const float4*>(&As[kk][ty * 8]);
            *reinterpret_cast<float4*>(&a[4]) = *reinterpret_cast<const float4*>(&As[kk][ty * 8 + 4]);
            *reinterpret_cast<float4*>(&b[0]) = *reinterpret_cast<const float4*>(&Bs[kk][tx * 8]);
            *reinterpret_cast<float4*>(&b[4]) = *reinterpret_cast<const float4*>(&Bs[kk][tx * 8 + 4]);
#pragma unroll
            for (int i = 0; i < 8; i++)
#pragma unroll
                for (int j = 0; j < 8; j++) acc[i][j] = fmaf(a[i], b[j], acc[i][j]);
        }
        __syncthreads();
    }

#pragma unroll
    for (int i = 0; i < 8; i++) {
        size_t r = rowbase + ty * 8 + i;
#pragma unroll
        for (int j = 0; j < 8; j++) {
            float v = acc[i][j];
            out[r * DDIM + tx * 8 + j] = (v > 0.f) ? v : 0.f;
        }
    }
}

// ---------------------------------------------------------------------------
extern "C" void kernel_launch(void* const* d_in, const int* in_sizes, int n_in,
                              void* d_out, int out_size) {
    const float* x_self  = (const float*)d_in[0];   // [1024,32,128]
    const float* x_neigh = (const float*)d_in[1];   // [1024,32,25,128]
    const float* w_feat  = (const float*)d_in[2];   // [128,128]
    const float* a_self  = (const float*)d_in[3];   // [128,1]
    const float* a_neigh = (const float*)d_in[4];   // [128,1]
    float*       out     = (float*)d_out;           // [1024,32,128]

    wa_kernel<<<16, 256>>>(w_feat, a_self, a_neigh);
    agg_kernel<<<BH, 128>>>(x_self, x_neigh);
    gemm_relu_kernel<<<BH / K2_BM, 256>>>(w_feat, out);
}

// round 4
// speedup vs baseline: 1.0591x; 1.0591x over previous
#include <cuda_runtime.h>
#include <cstdint>
#include <math.h>

// Problem constants: B=1024, H=32, N=25, F=D=128
#define BH      32768
#define NNEIGH  25
#define NK      26                 // self + neighbours
#define FDIM    128
#define DDIM    128
#define XN_ROW  (NNEIGH * FDIM)    // 3200 floats per (b,h)
#define GRIDSZ  304                // ~2 blocks per SM
#define THREADS 256

// ---------------------------------------------------------------------------
// cp.async helpers
// ---------------------------------------------------------------------------
__device__ __forceinline__ void cpasync16(unsigned saddr, const void* gptr) {
    asm volatile("cp.async.cg.shared.global [%0], [%1], 16;\n"
                 :: "r"(saddr), "l"(gptr));
}
#define CP_COMMIT() asm volatile("cp.async.commit_group;\n" ::: "memory")
#define CP_WAIT1()  asm volatile("cp.async.wait_group 1;\n" ::: "memory")

// ---------------------------------------------------------------------------
// Single fused kernel. Each block:
//   prologue: compute wa_s/wa_n = W@a (once), cache W column-halves in regs
//   loop rows (strided by GRIDSZ): cp.async double-buffered 26x128 tile,
//     scores -> softmax -> xagg (input space) -> GEMV from reg-W -> relu -> out
// ---------------------------------------------------------------------------
__global__ void __launch_bounds__(THREADS)
fused_gat_kernel(const float* __restrict__ x_self,
                 const float* __restrict__ x_neigh,
                 const float* __restrict__ W,
                 const float* __restrict__ a_s,
                 const float* __restrict__ a_n,
                 float* __restrict__ out) {
    __shared__ float xs[2][NK * FDIM];    // double-buffered tile (row0 = self)
    __shared__ float wa_s_sm[FDIM];
    __shared__ float wa_n_sm[FDIM];
    __shared__ float sc[32];              // [0..25] scores->probs, [26] self score
    __shared__ float xagg_sm[FDIM];

    const int t    = threadIdx.x;
    const int warp = t >> 5;
    const int lane = t & 31;

    // ---------------- prologue: wa = W @ a ----------------
    float asr[4], anr[4];
#pragma unroll
    for (int m = 0; m < 4; m++) {
        asr[m] = a_s[lane + 32 * m];
        anr[m] = a_n[lane + 32 * m];
    }
    // warp w computes wa for f in [w*16, w*16+16)
    for (int ff = 0; ff < 16; ff++) {
        const int f = warp * 16 + ff;
        const float* wr = W + (size_t)f * DDIM;
        float vs = 0.f, vn = 0.f;
#pragma unroll
        for (int m = 0; m < 4; m++) {
            float w = wr[lane + 32 * m];
            vs = fmaf(w, asr[m], vs);
            vn = fmaf(w, anr[m], vn);
        }
#pragma unroll
        for (int o = 16; o; o >>= 1) {
            vs += __shfl_xor_sync(0xffffffffu, vs, o);
            vn += __shfl_xor_sync(0xffffffffu, vn, o);
        }
        if (lane == 0) { wa_s_sm[f] = vs; wa_n_sm[f] = vn; }
    }
    __syncthreads();

    // per-lane wa register copies (same for every warp)
    float was[4], wan[4];
#pragma unroll
    for (int m = 0; m < 4; m++) {
        was[m] = wa_s_sm[lane + 32 * m];
        wan[m] = wa_n_sm[lane + 32 * m];
    }

    // ---------------- W register cache ----------------
    // warp w covers cols d = w*16 .. w*16+15; lanes 0-15 hold f-half 0,
    // lanes 16-31 hold f-half 1. Wreg[i] = W[(h*64+i)*128 + d].
    const int h = lane >> 4;              // f-half
    const int d = warp * 16 + (lane & 15);
    float Wreg[64];
#pragma unroll
    for (int i = 0; i < 64; i++)
        Wreg[i] = W[(size_t)(h * 64 + i) * DDIM + d];

    // ---------------- pipelined row loop ----------------
    // stage(row, buf): rows 1..25 = neighbours (800 float4), row 0 = self (32 float4)
    int row = blockIdx.x;
    int cur = 0;

    {   // prologue stage of first row
        unsigned sb = (unsigned)__cvta_generic_to_shared(&xs[0][0]);
        const float4* xn = reinterpret_cast<const float4*>(x_neigh + (size_t)row * XN_ROW);
#pragma unroll
        for (int i = t; i < XN_ROW / 4; i += THREADS)
            cpasync16(sb + (FDIM + 4 * i) * 4, xn + i);
        if (t < 32)
            cpasync16(sb + t * 16, x_self + (size_t)row * FDIM + t * 4);
        CP_COMMIT();
    }

    while (row < BH) {
        const int nrow = row + GRIDSZ;
        // stage next row into the other buffer (empty commit keeps group counts uniform)
        if (nrow < BH) {
            unsigned sb = (unsigned)__cvta_generic_to_shared(&xs[cur ^ 1][0]);
            const float4* xn = reinterpret_cast<const float4*>(x_neigh + (size_t)nrow * XN_ROW);
#pragma unroll
            for (int i = t; i < XN_ROW / 4; i += THREADS)
                cpasync16(sb + (FDIM + 4 * i) * 4, xn + i);
            if (t < 32)
                cpasync16(sb + t * 16, x_self + (size_t)nrow * FDIM + t * 4);
        }
        CP_COMMIT();
        CP_WAIT1();            // oldest group (current row's tile) complete
        __syncthreads();

        const float* xb = &xs[cur][0];

        // ---- 27 dots: warp w owns k = w, w+8, w+16, w+24 ----
#pragma unroll
        for (int j = 0; j < 4; j++) {
            const int k = warp + 8 * j;
            if (k <= 26) {
                const int r = (k == 26) ? 0 : k;
                const float* xr = xb + r * FDIM;
                float v;
                if (k == 26) {
                    v =      xr[lane]      * was[0];
                    v = fmaf(xr[lane + 32], was[1], v);
                    v = fmaf(xr[lane + 64], was[2], v);
                    v = fmaf(xr[lane + 96], was[3], v);
                } else {
                    v =      xr[lane]      * wan[0];
                    v = fmaf(xr[lane + 32], wan[1], v);
                    v = fmaf(xr[lane + 64], wan[2], v);
                    v = fmaf(xr[lane + 96], wan[3], v);
                }
#pragma unroll
                for (int o = 16; o; o >>= 1) v += __shfl_xor_sync(0xffffffffu, v, o);
                if (lane == 0) sc[k] = v;
            }
        }
        __syncthreads();

        // ---- softmax over 26 entries (warp 0) ----
        if (warp == 0) {
            float ss = sc[26];
            float u  = -INFINITY;
            if (lane < NK) {
                u = ss + sc[lane];
                u = (u > 0.f) ? u : 0.2f * u;       // LeakyReLU(0.2)
            }
            float m = u;
#pragma unroll
            for (int o = 16; o; o >>= 1) m = fmaxf(m, __shfl_xor_sync(0xffffffffu, m, o));
            float e = (lane < NK) ? expf(u - m) : 0.f;
            float s = e;
#pragma unroll
            for (int o = 16; o; o >>= 1) s += __shfl_xor_sync(0xffffffffu, s, o);
            if (lane < NK) sc[lane] = e / s;
        }
        __syncthreads();

        // ---- xagg[f] = sum_k p_k * x_all[k][f]  (threads 0..127) ----
        if (t < FDIM) {
            float acc = 0.f;
#pragma unroll
            for (int k = 0; k < NK; k++) acc = fmaf(sc[k], xb[k * FDIM + t], acc);
            xagg_sm[t] = acc;
        }
        __syncthreads();

        // ---- GEMV from register-cached W; halves combined via shfl ----
        {
            float o = 0.f;
            const float4* xa4 = reinterpret_cast<const float4*>(xagg_sm);
#pragma unroll
            for (int j = 0; j < 16; j++) {
                float4 xa = xa4[h * 16 + j];        // 2-way broadcast per warp
                o = fmaf(xa.x, Wreg[4 * j],     o);
                o = fmaf(xa.y, Wreg[4 * j + 1], o);
                o = fmaf(xa.z, Wreg[4 * j + 2], o);
                o = fmaf(xa.w, Wreg[4 * j + 3], o);
            }
            o += __shfl_xor_sync(0xffffffffu, o, 16);   // combine f-halves
            if (h == 0)
                out[(size_t)row * DDIM + d] = (o > 0.f) ? o : 0.f;
        }
        // NOTE: no end-of-iteration sync needed: next stage writes buf[cur^1],
        // and all xs reads of buf[cur] finished before the xagg sync above.

        row = nrow;
        cur ^= 1;
    }
}

// ---------------------------------------------------------------------------
extern "C" void kernel_launch(void* const* d_in, const int* in_sizes, int n_in,
                              void* d_out, int out_size) {
    const float* x_self  = (const float*)d_in[0];   // [1024,32,128]
    const float* x_neigh = (const float*)d_in[1];   // [1024,32,25,128]
    const float* w_feat  = (const float*)d_in[2];   // [128,128]
    const float* a_self  = (const float*)d_in[3];   // [128,1]
    const float* a_neigh = (const float*)d_in[4];   // [128,1]
    float*       out     = (float*)d_out;           // [1024,32,128]

    fused_gat_kernel<<<GRIDSZ, THREADS>>>(x_self, x_neigh, w_feat,
                                          a_self, a_neigh, out);
}

// round 5
// speedup vs baseline: 1.2709x; 1.2000x over previous
#include <cuda_runtime.h>
#include <cstdint>
#include <math.h>

// Problem constants: B=1024, H=32, N=25, F=D=128
#define BH      32768
#define NK      26                 // self + neighbours
#define FDIM    128
#define DDIM    128
#define XN_ROW  (25 * 128)         // 3200 floats per (b,h)
#define GRIDSZ  304                // 2 blocks/SM x 152 SMs (GB300)
#define THREADS 256

typedef unsigned long long ull;

__device__ __forceinline__ void cpasync16(unsigned saddr, const void* gptr) {
    asm volatile("cp.async.cg.shared.global [%0], [%1], 16;\n"
                 :: "r"(saddr), "l"(gptr));
}
#define CP_COMMIT() asm volatile("cp.async.commit_group;\n" ::: "memory")
#define CP_WAIT2()  asm volatile("cp.async.wait_group 2;\n" ::: "memory")

__global__ void __launch_bounds__(THREADS, 2)
fused_gat_kernel(const float* __restrict__ x_self,
                 const float* __restrict__ x_neigh,
                 const float* __restrict__ W,
                 const float* __restrict__ a_s,
                 const float* __restrict__ a_n,
                 float* __restrict__ out) {
    __shared__ __align__(16) float xs[3][NK * FDIM];   // 3-deep ring (row0 = self)
    __shared__ float wa_s_sm[FDIM];
    __shared__ float wa_n_sm[FDIM];
    __shared__ float sc[32];                            // raw scores [0..26]
    __shared__ __align__(16) float xagg_sm[FDIM];

    const int t    = threadIdx.x;
    const int warp = t >> 5;
    const int lane = t & 31;

    // ---------------- prologue: wa = W @ a  (2 threads per f) ----------------
    {
        const int f  = t >> 1, hf = t & 1;
        const float* wr = W + (size_t)f * DDIM + hf * 64;
        const float* as = a_s + hf * 64;
        const float* an = a_n + hf * 64;
        float vs = 0.f, vn = 0.f;
#pragma unroll
        for (int j = 0; j < 64; j++) {
            float w = wr[j];
            vs = fmaf(w, as[j], vs);
            vn = fmaf(w, an[j], vn);
        }
        vs += __shfl_xor_sync(0xffffffffu, vs, 1);
        vn += __shfl_xor_sync(0xffffffffu, vn, 1);
        if (!hf) { wa_s_sm[f] = vs; wa_n_sm[f] = vn; }
    }
    __syncthreads();

    // per-lane wa float4 slices for the score pass (8 lanes span 128 floats)
    const int s8 = lane & 7;       // sub-lane within a dot
    const int g4 = lane >> 3;      // dot group within warp
    float4 was4[4], wan4[4];
#pragma unroll
    for (int j = 0; j < 4; j++) {
        was4[j] = reinterpret_cast<const float4*>(wa_s_sm)[s8 + 8 * j];
        wan4[j] = reinterpret_cast<const float4*>(wa_n_sm)[s8 + 8 * j];
    }

    // W register cache, packed as f32x2 pairs along f.
    // warp w covers d = w*16 + (lane&15); lanes 0-15: f-half 0, 16-31: f-half 1.
    const int h = lane >> 4;
    const int d = warp * 16 + (lane & 15);
    ull Wreg2[32];
#pragma unroll
    for (int i = 0; i < 32; i++) {
        int f = h * 64 + 2 * i;
        unsigned lo = __float_as_uint(W[(size_t)f * DDIM + d]);
        unsigned hi = __float_as_uint(W[(size_t)(f + 1) * DDIM + d]);
        Wreg2[i] = ((ull)hi << 32) | lo;
    }

    // ---------------- tile stage helper ----------------
    auto stage = [&](int r, int b) {
        unsigned sb = (unsigned)__cvta_generic_to_shared(&xs[b][0]);
        const float4* xn = reinterpret_cast<const float4*>(x_neigh + (size_t)r * XN_ROW);
#pragma unroll 4
        for (int i = t; i < XN_ROW / 4; i += THREADS)
            cpasync16(sb + (FDIM + 4 * i) * 4, xn + i);
        if (t < 32)
            cpasync16(sb + t * 16, x_self + (size_t)r * FDIM + t * 4);
    };

    int row = blockIdx.x;
    stage(row, 0); CP_COMMIT();
    if (row + GRIDSZ < BH) stage(row + GRIDSZ, 1);
    CP_COMMIT();

    int bi = 0;
    while (row < BH) {
        // stage row+2G into ring slot (bi+2)%3; keep group counts uniform
        {
            int r2 = row + 2 * GRIDSZ;
            int b2 = bi + 2; if (b2 >= 3) b2 -= 3;
            if (r2 < BH) stage(r2, b2);
            CP_COMMIT();
        }
        CP_WAIT2();
        __syncthreads();                       // B1: current tile visible

        const float* xb = &xs[bi][0];

        // ---- scores: all 27 dots in one pass, 8 lanes per dot ----
        {
            const int k = warp * 4 + g4;       // dot index (valid: warp<7, k<27)
            float v = 0.f;
            if (warp < 7 && k < 27) {
                const float4* xr = reinterpret_cast<const float4*>(
                    xb + ((k == 26) ? 0 : k) * FDIM);
#pragma unroll
                for (int j = 0; j < 4; j++) {
                    float4 x4 = xr[s8 + 8 * j];
                    float4 w4 = (k == 26) ? was4[j] : wan4[j];
                    v = fmaf(x4.x, w4.x, v);
                    v = fmaf(x4.y, w4.y, v);
                    v = fmaf(x4.z, w4.z, v);
                    v = fmaf(x4.w, w4.w, v);
                }
            }
            v += __shfl_xor_sync(0xffffffffu, v, 1);
            v += __shfl_xor_sync(0xffffffffu, v, 2);
            v += __shfl_xor_sync(0xffffffffu, v, 4);
            if (warp < 7 && (lane & 7) == 0) {
                if (k < 27) sc[k] = v;
            }
        }
        __syncthreads();                       // B2: scores visible

        // ---- softmax (per-warp redundant, warps 0-3) + xagg ----
        if (warp < 4) {
            float v  = (lane < 27) ? sc[lane] : 0.f;
            float ss = __shfl_sync(0xffffffffu, v, 26);
            float u  = (lane < NK) ? ss + v : -INFINITY;
            u = (u > 0.f) ? u : 0.2f * u;      // LeakyReLU(0.2)
            float m = u;
#pragma unroll
            for (int o = 16; o; o >>= 1) m = fmaxf(m, __shfl_xor_sync(0xffffffffu, m, o));
            float e = (lane < NK) ? __expf(u - m) : 0.f;
            float sm = e;
#pragma unroll
            for (int o = 16; o; o >>= 1) sm += __shfl_xor_sync(0xffffffffu, sm, o);
            float p = __fdividef(e, sm);

            // xagg[f] = sum_k p_k * x_all[k][f]; probs via in-warp shuffle
            const float* xc = xb + t;          // f = t (t < 128)
            float acc = 0.f;
#pragma unroll
            for (int k = 0; k < NK; k++)
                acc = fmaf(__shfl_sync(0xffffffffu, p, k), xc[k * FDIM], acc);
            xagg_sm[t] = acc;
        }
        __syncthreads();                       // B3: xagg visible

        // ---- GEMV from packed register W (FFMA2), halves combined via shfl ----
        {
            ull acc2 = 0;                      // {0.f, 0.f}
            const ull* xa2 = reinterpret_cast<const ull*>(xagg_sm) + h * 32;
#pragma unroll
            for (int i = 0; i < 32; i++) {
                ull x2 = xa2[i];               // LDS.64 broadcast pair
                asm volatile("fma.rn.f32x2 %0, %1, %2, %0;\n"
                             : "+l"(acc2) : "l"(x2), "l"(Wreg2[i]));
            }
            float o = __uint_as_float((unsigned)acc2) +
                      __uint_as_float((unsigned)(acc2 >> 32));
            o += __shfl_xor_sync(0xffffffffu, o, 16);   // combine f-halves
            if (h == 0)
                out[(size_t)row * DDIM + d] = (o > 0.f) ? o : 0.f;
        }

        row += GRIDSZ;
        bi += 1; if (bi >= 3) bi = 0;
    }
}

// ---------------------------------------------------------------------------
extern "C" void kernel_launch(void* const* d_in, const int* in_sizes, int n_in,
                              void* d_out, int out_size) {
    const float* x_self  = (const float*)d_in[0];   // [1024,32,128]
    const float* x_neigh = (const float*)d_in[1];   // [1024,32,25,128]
    const float* w_feat  = (const float*)d_in[2];   // [128,128]
    const float* a_self  = (const float*)d_in[3];   // [128,1]
    const float* a_neigh = (const float*)d_in[4];   // [128,1]
    float*       out     = (float*)d_out;           // [1024,32,128]

    fused_gat_kernel<<<GRIDSZ, THREADS>>>(x_self, x_neigh, w_feat,
                                          a_self, a_neigh, out);
}

// round 6
// speedup vs baseline: 1.2895x; 1.0146x over previous
#include <cuda_runtime.h>
#include <cstdint>
#include <math.h>

// Problem constants: B=1024, H=32, N=25, F=D=128
#define BH      32768
#define NK      26                 // self + neighbours
#define FDIM    128
#define DDIM    128
#define XN_ROW  (25 * 128)         // 3200 floats per (b,h)
#define GRIDSZ  304                // 2 blocks/SM x 152 SMs (GB300)
#define THREADS 256

typedef unsigned long long ull;

__device__ __forceinline__ void cpasync16(unsigned saddr, const void* gptr) {
    asm volatile("cp.async.cg.shared.global [%0], [%1], 16;\n"
                 :: "r"(saddr), "l"(gptr));
}
#define CP_COMMIT() asm volatile("cp.async.commit_group;\n" ::: "memory")
#define CP_WAIT1()  asm volatile("cp.async.wait_group 1;\n" ::: "memory")

__global__ void __launch_bounds__(THREADS, 2)
fused_gat_kernel(const float* __restrict__ x_self,
                 const float* __restrict__ x_neigh,
                 const float* __restrict__ W,
                 const float* __restrict__ a_s,
                 const float* __restrict__ a_n,
                 float* __restrict__ out) {
    __shared__ __align__(16) float xs[4][NK * FDIM];   // 4-slot ring, pairs {0,1},{2,3}
    __shared__ __align__(16) float wa_s_sm[FDIM];
    __shared__ float wa_n_sm[FDIM];
    __shared__ float sc[2][32];                        // raw scores per pair-row
    __shared__ __align__(16) float xagg_sm[2][FDIM];

    const int t    = threadIdx.x;
    const int warp = t >> 5;
    const int lane = t & 31;

    // ---------------- prologue: wa = W @ a  (2 threads per f) ----------------
    {
        const int f  = t >> 1, hf = t & 1;
        const float* wr = W + (size_t)f * DDIM + hf * 64;
        const float* as = a_s + hf * 64;
        const float* an = a_n + hf * 64;
        float vs = 0.f, vn = 0.f;
#pragma unroll
        for (int j = 0; j < 64; j++) {
            float w = wr[j];
            vs = fmaf(w, as[j], vs);
            vn = fmaf(w, an[j], vn);
        }
        vs += __shfl_xor_sync(0xffffffffu, vs, 1);
        vn += __shfl_xor_sync(0xffffffffu, vn, 1);
        if (!hf) { wa_s_sm[f] = vs; wa_n_sm[f] = vn; }
    }
    __syncthreads();

    // score-pass mapping: 4 lanes per dot, 8 dots per warp
    const int s4   = lane & 3;        // sub-lane within a dot
    const int g8   = lane >> 2;       // dot group within warp (0..7)
    const int kdot = (warp & 3) * 8 + g8;   // 0..31; valid if < 27
    const int rsel = warp >> 2;       // 0 = row A (warps 0-3), 1 = row B (warps 4-7)

    float4 wan4[8];                   // wa_n slice for this sub-lane
#pragma unroll
    for (int j = 0; j < 8; j++)
        wan4[j] = reinterpret_cast<const float4*>(wa_n_sm)[s4 + 4 * j];

    // W register cache, packed f32x2 along f.
    // warp w covers d = w*16 + (lane&15); lanes 0-15: f-half 0, 16-31: f-half 1.
    const int h = lane >> 4;
    const int d = warp * 16 + (lane & 15);
    ull Wreg2[32];
#pragma unroll
    for (int i = 0; i < 32; i++) {
        int f = h * 64 + 2 * i;
        unsigned lo = __float_as_uint(W[(size_t)f * DDIM + d]);
        unsigned hi = __float_as_uint(W[(size_t)(f + 1) * DDIM + d]);
        Wreg2[i] = ((ull)hi << 32) | lo;
    }

    // ---------------- tile stage helper ----------------
    auto stage = [&](int r, int b) {
        unsigned sb = (unsigned)__cvta_generic_to_shared(&xs[b][0]);
        const float4* xn = reinterpret_cast<const float4*>(x_neigh + (size_t)r * XN_ROW);
#pragma unroll 4
        for (int i = t; i < XN_ROW / 4; i += THREADS)
            cpasync16(sb + (FDIM + 4 * i) * 4, xn + i);
        if (t < 32)
            cpasync16(sb + t * 16, x_self + (size_t)r * FDIM + t * 4);
    };

    int row = blockIdx.x;
    const int G = GRIDSZ;

    stage(row, 0);
    if (row + G < BH) stage(row + G, 1);
    CP_COMMIT();

    int pp = 0;                        // current pair slots {pp, pp+1}
    while (row < BH) {
        // prefetch next pair into opposite slots
        {
            int r2 = row + 2 * G, r3 = row + 3 * G;
            int q = pp ^ 2;
            if (r2 < BH) stage(r2, q);
            if (r3 < BH) stage(r3, q + 1);
            CP_COMMIT();
        }
        CP_WAIT1();
        __syncthreads();               // B1: current pair visible

        const float* xb = &xs[pp + rsel][0];

        // ---- scores: 54 dots (27 per row), 4 lanes per dot ----
        {
            float v0 = 0.f, v1 = 0.f;
            if (kdot < 27) {
                const float4* xr = reinterpret_cast<const float4*>(
                    xb + ((kdot == 26) ? 0 : kdot) * FDIM);
                if (kdot == 26) {      // self score uses wa_s (from smem; 2 groups total)
                    const float4* ws = reinterpret_cast<const float4*>(wa_s_sm);
#pragma unroll
                    for (int j = 0; j < 8; j++) {
                        float4 x4 = xr[s4 + 4 * j];
                        float4 w4 = ws[s4 + 4 * j];
                        if (j & 1) { v1 = fmaf(x4.x, w4.x, v1); v1 = fmaf(x4.y, w4.y, v1);
                                     v1 = fmaf(x4.z, w4.z, v1); v1 = fmaf(x4.w, w4.w, v1); }
                        else       { v0 = fmaf(x4.x, w4.x, v0); v0 = fmaf(x4.y, w4.y, v0);
                                     v0 = fmaf(x4.z, w4.z, v0); v0 = fmaf(x4.w, w4.w, v0); }
                    }
                } else {
#pragma unroll
                    for (int j = 0; j < 8; j++) {
                        float4 x4 = xr[s4 + 4 * j];
                        float4 w4 = wan4[j];
                        if (j & 1) { v1 = fmaf(x4.x, w4.x, v1); v1 = fmaf(x4.y, w4.y, v1);
                                     v1 = fmaf(x4.z, w4.z, v1); v1 = fmaf(x4.w, w4.w, v1); }
                        else       { v0 = fmaf(x4.x, w4.x, v0); v0 = fmaf(x4.y, w4.y, v0);
                                     v0 = fmaf(x4.z, w4.z, v0); v0 = fmaf(x4.w, w4.w, v0); }
                    }
                }
            }
            float v = v0 + v1;
            v += __shfl_xor_sync(0xffffffffu, v, 1);
            v += __shfl_xor_sync(0xffffffffu, v, 2);
            if (s4 == 0 && kdot < 27) sc[rsel][kdot] = v;
        }
        __syncthreads();               // B2: scores visible

        // ---- softmax (redundant per warp) + xagg: warps 0-3 = A, 4-7 = B ----
        {
            float v  = (lane < 27) ? sc[rsel][lane] : 0.f;
            float ss = __shfl_sync(0xffffffffu, v, 26);
            float u  = (lane < NK) ? ss + v : -INFINITY;
            u = (u > 0.f) ? u : 0.2f * u;          // LeakyReLU(0.2)
            float m = u;
#pragma unroll
            for (int o = 16; o; o >>= 1) m = fmaxf(m, __shfl_xor_sync(0xffffffffu, m, o));
            float e  = (lane < NK) ? __expf(u - m) : 0.f;
            float sm = e;
#pragma unroll
            for (int o = 16; o; o >>= 1) sm += __shfl_xor_sync(0xffffffffu, sm, o);
            float p = __fdividef(e, sm);

            const int fidx = t & 127;              // f index within the row
            const float* xc = &xs[pp + rsel][0] + fidx;
            float acc = 0.f;
#pragma unroll
            for (int k = 0; k < NK; k++)
                acc = fmaf(__shfl_sync(0xffffffffu, p, k), xc[k * FDIM], acc);
            xagg_sm[rsel][fidx] = acc;
        }
        __syncthreads();               // B3: xagg visible

        // ---- GEMV (both rows) from packed register W; LDS.128 broadcasts ----
#pragma unroll
        for (int r = 0; r < 2; r++) {
            int orow = row + r * G;
            if (orow < BH) {
                ull a0 = 0, a1 = 0;
                const longlong2* xa =
                    reinterpret_cast<const longlong2*>(&xagg_sm[r][h * 64]);
#pragma unroll
                for (int i = 0; i < 16; i++) {
                    longlong2 q = xa[i];           // LDS.128 broadcast (f pair x2)
                    asm volatile("fma.rn.f32x2 %0, %1, %2, %0;\n"
                                 : "+l"(a0) : "l"((ull)q.x), "l"(Wreg2[2 * i]));
                    asm volatile("fma.rn.f32x2 %0, %1, %2, %0;\n"
                                 : "+l"(a1) : "l"((ull)q.y), "l"(Wreg2[2 * i + 1]));
                }
                float o = __uint_as_float((unsigned)a0) +
                          __uint_as_float((unsigned)(a0 >> 32)) +
                          __uint_as_float((unsigned)a1) +
                          __uint_as_float((unsigned)(a1 >> 32));
                o += __shfl_xor_sync(0xffffffffu, o, 16);   // combine f-halves
                if (h == 0)
                    out[(size_t)orow * DDIM + d] = (o > 0.f) ? o : 0.f;
            }
        }

        row += 2 * G;
        pp ^= 2;
    }
}

// ---------------------------------------------------------------------------
extern "C" void kernel_launch(void* const* d_in, const int* in_sizes, int n_in,
                              void* d_out, int out_size) {
    const float* x_self  = (const float*)d_in[0];   // [1024,32,128]
    const float* x_neigh = (const float*)d_in[1];   // [1024,32,25,128]
    const float* w_feat  = (const float*)d_in[2];   // [128,128]
    const float* a_self  = (const float*)d_in[3];   // [128,1]
    const float* a_neigh = (const float*)d_in[4];   // [128,1]
    float*       out     = (float*)d_out;           // [1024,32,128]

    fused_gat_kernel<<<GRIDSZ, THREADS>>>(x_self, x_neigh, w_feat,
                                          a_self, a_neigh, out);
}